// round 14
// baseline (speedup 1.0000x reference)
#include <cuda_runtime.h>
#include <cuda_bf16.h>
#include <math.h>
#include <stdint.h>

#define NN   40000
#define NE   640000
#define FIN  512
#define HH   128
#define CO   40
#define GB_GEMM  313                  // gemm blocks
#define GB_ZERO  ((NN + 255) / 256)   // 157 zero blocks
#define GB_FUSEW ((HH*HH + HH*CO) / 256)  // 84 fuse_w blocks
#define GB_TOTAL (GB_GEMM + GB_ZERO + GB_FUSEW + 1)

// ---------------- scratch (device globals) ----------------
__device__ __align__(16) float g_xh [NN*HH];
__device__ __align__(16) float g_tx1[NN*HH];
__device__ __align__(16) float g_s  [NN*HH];
__device__ __align__(16) float g_xc [NN*HH];
__device__ __align__(16) float g_w1p[HH*HH];   // lw1 @ pw2
__device__ __align__(16) float g_b1p[HH];      // lb1 @ pw2 + pb2
__device__ __align__(16) float g_w2p[HH*CO];   // lw2 @ cls_w
__device__ __align__(16) float g_b2p[CO];      // lb2 @ cls_w + cls_b
__device__ float g_deg   [NN];
__device__ float g_dis   [NN];
__device__ float g_loopw [NN];
__device__ float g_invcnt[NN];
__device__ __align__(16) int g_cnt   [NN + 64];
__device__ int   g_cursor[NN];
__device__ int   g_rowptr[NN + 1];
__device__ int   g_bsum  [160];
__device__ __align__(16) int4 g_emeta[NE];

// ---------------- graph prep ----------------
__global__ void prep_edge_kernel(const int* __restrict__ ei, const float* __restrict__ w) {
    int e = blockIdx.x * blockDim.x + threadIdx.x;
    if (e >= NE) return;
    int s = ei[e], d = ei[NE + e];
    float we = w[e];
    if (s != d) {
        atomicAdd(&g_deg[s], we);
        atomicAdd(&g_cnt[d], 1);
    } else {
        g_loopw[s] = we;
    }
}

// ---------------- scan phase 1: block sums ----------------
__global__ __launch_bounds__(256)
void scan1_kernel() {
    __shared__ int swarp[8];
    int idx = blockIdx.x * 256 + threadIdx.x;
    int lane = threadIdx.x & 31, wid = threadIdx.x >> 5;
    int v = (idx < NN) ? g_cnt[idx] : 0;
    int sum = v;
    #pragma unroll
    for (int o = 16; o > 0; o >>= 1) sum += __shfl_xor_sync(0xffffffffu, sum, o);
    if (lane == 0) swarp[wid] = sum;
    __syncthreads();
    if (threadIdx.x == 0) {
        int t = 0;
        #pragma unroll
        for (int i = 0; i < 8; i++) t += swarp[i];
        g_bsum[blockIdx.x] = t;
    }
}

// ---------------- scan phase 2 (merged): rowptr emit + node prep ----------------
__global__ __launch_bounds__(256)
void scan3m_kernel() {
    __shared__ int swarp[8];
    __shared__ int s_off;
    int tidx = threadIdx.x;
    int lane = tidx & 31, wid = tidx >> 5;

    if (wid == 0) {
        int acc = 0;
        for (int i = lane; i < blockIdx.x; i += 32) acc += g_bsum[i];
        #pragma unroll
        for (int o = 16; o > 0; o >>= 1) acc += __shfl_xor_sync(0xffffffffu, acc, o);
        if (lane == 0) s_off = acc;
    }

    int idx = blockIdx.x * 256 + tidx;
    int v = (idx < NN) ? g_cnt[idx] : 0;
    int incl = v;
    #pragma unroll
    for (int o = 1; o < 32; o <<= 1) {
        int u = __shfl_up_sync(0xffffffffu, incl, o);
        if (lane >= o) incl += u;
    }
    if (lane == 31) swarp[wid] = incl;
    __syncthreads();
    if (wid == 0 && lane < 8) {
        int x = swarp[lane];
        int ix = x;
        #pragma unroll
        for (int o = 1; o < 8; o <<= 1) {
            int u = __shfl_up_sync(0xffu, ix, o);
            if (lane >= o) ix += u;
        }
        swarp[lane] = ix - x;
    }
    __syncthreads();
    int excl = s_off + swarp[wid] + incl - v;
    if (idx < NN) {
        g_rowptr[idx] = excl;
        float dg = g_deg[idx];
        g_dis[idx]    = (dg > 0.0f) ? rsqrtf(dg) : 0.0f;
        g_invcnt[idx] = 1.0f / ((float)v + 1.0f);
    }
    if (idx == NN - 1) g_rowptr[NN] = excl + v;
}

// ---------------- fill CSR ----------------
__global__ void fill_kernel(const int* __restrict__ ei, const float* __restrict__ w) {
    int e = blockIdx.x * blockDim.x + threadIdx.x;
    if (e >= NE) return;
    int s = ei[e], d = ei[NE + e];
    if (s == d) return;
    float we   = w[e];
    float coef = -g_dis[s] * we * g_dis[d];
    int pos = g_rowptr[d] + atomicAdd(&g_cursor[d], 1);
    g_emeta[pos] = make_int4(s, __float_as_int(we), __float_as_int(coef), 0);
}

// ---------------- CSR gather-reduce: 64 threads/node, float2 lanes, unroll-8 ----------------
__global__ __launch_bounds__(256)
void aggregate_kernel(const float2* __restrict__ xh,
                      float2* __restrict__ tx1, float2* __restrict__ s) {
    int n    = (blockIdx.x * blockDim.x + threadIdx.x) >> 6;   // 64 threads per node
    int lane = threadIdx.x & 63;
    if (n >= NN) return;
    int beg = g_rowptr[n], end = g_rowptr[n + 1];

    float lw = g_loopw[n];
    float2 xv = xh[n * 64 + lane];
    float ax = 0.f, ay = 0.f;
    float bx = lw * xv.x, by = lw * xv.y;

    int e = beg;
    int end8 = beg + ((end - beg) & ~7);
    if (e < end8) {
        int4 m0 = g_emeta[e+0], m1 = g_emeta[e+1], m2 = g_emeta[e+2], m3 = g_emeta[e+3];
        int4 m4 = g_emeta[e+4], m5 = g_emeta[e+5], m6 = g_emeta[e+6], m7 = g_emeta[e+7];
        while (e < end8) {
            float2 v0 = xh[m0.x * 64 + lane];
            float2 v1 = xh[m1.x * 64 + lane];
            float2 v2 = xh[m2.x * 64 + lane];
            float2 v3 = xh[m3.x * 64 + lane];
            float2 v4 = xh[m4.x * 64 + lane];
            float2 v5 = xh[m5.x * 64 + lane];
            float2 v6 = xh[m6.x * 64 + lane];
            float2 v7 = xh[m7.x * 64 + lane];
            float w0 = __int_as_float(m0.y), c0 = __int_as_float(m0.z);
            float w1 = __int_as_float(m1.y), c1 = __int_as_float(m1.z);
            float w2 = __int_as_float(m2.y), c2 = __int_as_float(m2.z);
            float w3 = __int_as_float(m3.y), c3 = __int_as_float(m3.z);
            float w4 = __int_as_float(m4.y), c4 = __int_as_float(m4.z);
            float w5 = __int_as_float(m5.y), c5 = __int_as_float(m5.z);
            float w6 = __int_as_float(m6.y), c6 = __int_as_float(m6.z);
            float w7 = __int_as_float(m7.y), c7 = __int_as_float(m7.z);
            e += 8;
            if (e < end8) {
                m0 = g_emeta[e+0]; m1 = g_emeta[e+1]; m2 = g_emeta[e+2]; m3 = g_emeta[e+3];
                m4 = g_emeta[e+4]; m5 = g_emeta[e+5]; m6 = g_emeta[e+6]; m7 = g_emeta[e+7];
            }
            ax += c0*v0.x + c1*v1.x + c2*v2.x + c3*v3.x
                + c4*v4.x + c5*v5.x + c6*v6.x + c7*v7.x;
            ay += c0*v0.y + c1*v1.y + c2*v2.y + c3*v3.y
                + c4*v4.y + c5*v5.y + c6*v6.y + c7*v7.y;
            bx += w0*v0.x + w1*v1.x + w2*v2.x + w3*v3.x
                + w4*v4.x + w5*v5.x + w6*v6.x + w7*v7.x;
            by += w0*v0.y + w1*v1.y + w2*v2.y + w3*v3.y
                + w4*v4.y + w5*v5.y + w6*v6.y + w7*v7.y;
        }
    }
    for (; e < end; e++) {
        int4 m = g_emeta[e];
        float we = __int_as_float(m.y);
        float cf = __int_as_float(m.z);
        float2 v = xh[m.x * 64 + lane];
        ax += cf * v.x; ay += cf * v.y;
        bx += we * v.x; by += we * v.y;
    }
    float ic = g_invcnt[n];
    tx1[n * 64 + lane] = make_float2(ax, ay);
    s  [n * 64 + lane] = make_float2(bx * ic, by * ic);
}

// ---------------- common GEMM helpers ----------------
__device__ __forceinline__ void cp16(uint32_t dst, const void* src, bool valid) {
    int sz = valid ? 16 : 0;
    asm volatile("cp.async.cg.shared.global [%0], [%1], 16, %2;"
                 :: "r"(dst), "l"(src), "r"(sz));
}
#define CP_COMMIT() asm volatile("cp.async.commit_group;")
#define CP_WAIT(N)  asm volatile("cp.async.wait_group %0;" :: "n"(N))

__device__ __forceinline__ uint32_t ldtf(float x) {
    uint32_t u;
    asm("cvt.rna.tf32.f32 %0, %1;" : "=r"(u) : "f"(x));
    return u;
}

#define MMA_TF32(acc, af, bf)                                                   \
    asm volatile(                                                               \
        "mma.sync.aligned.m16n8k8.row.col.f32.tf32.tf32.f32 "                   \
        "{%0,%1,%2,%3}, {%4,%5,%6,%7}, {%8,%9}, {%0,%1,%2,%3};"                 \
        : "+f"((acc)[0]), "+f"((acc)[1]), "+f"((acc)[2]), "+f"((acc)[3])        \
        : "r"((af)[0]), "r"((af)[1]), "r"((af)[2]), "r"((af)[3]),               \
          "r"((bf)[0]), "r"((bf)[1]))

#define A_TILE_F (128 * 20)
#define B_TILE_F (16 * 136)

// ---------------- cell-1 pre-GEMM fused with zero + fuse_w + fuse_bias tails ----------------
#define SMEM_GEMM ((4 * A_TILE_F + 4 * B_TILE_F) * 4)

__global__ __launch_bounds__(256)
void gemm_pre_zero_kernel(const float* __restrict__ A, const float* __restrict__ B,
                          const float* __restrict__ bias, float* __restrict__ C,
                          int Nrows, int K,
                          const float* __restrict__ lw1, const float* __restrict__ pw2,
                          const float* __restrict__ lw2, const float* __restrict__ clsw,
                          const float* __restrict__ lb1, const float* __restrict__ pb2,
                          const float* __restrict__ lb2, const float* __restrict__ clsb) {
    // tail region 1: zero graph-prep buffers
    if (blockIdx.x >= GB_GEMM && blockIdx.x < GB_GEMM + GB_ZERO) {
        int n = (blockIdx.x - GB_GEMM) * 256 + threadIdx.x;
        if (n < NN) { g_deg[n] = 0.0f; g_loopw[n] = 1.0f; g_cnt[n] = 0; g_cursor[n] = 0; }
        return;
    }
    // tail region 2: fuse_w  (lw1@pw2 then lw2@cls_w)
    if (blockIdx.x >= GB_GEMM + GB_ZERO && blockIdx.x < GB_GEMM + GB_ZERO + GB_FUSEW) {
        int idx = (blockIdx.x - GB_GEMM - GB_ZERO) * 256 + threadIdx.x;
        if (idx < HH * HH) {
            int r = idx / HH, c = idx % HH;
            float acc = 0.0f;
            #pragma unroll 8
            for (int k = 0; k < HH; k++) acc += lw1[r * HH + k] * pw2[k * HH + c];
            g_w1p[idx] = acc;
        } else if (idx < HH * HH + HH * CO) {
            int t = idx - HH * HH;
            int r = t / CO, c = t % CO;
            float acc = 0.0f;
            #pragma unroll 8
            for (int k = 0; k < HH; k++) acc += lw2[r * HH + k] * clsw[k * CO + c];
            g_w2p[t] = acc;
        }
        return;
    }
    // tail region 3: fuse_bias
    if (blockIdx.x == GB_GEMM + GB_ZERO + GB_FUSEW) {
        int j = threadIdx.x;
        if (j < HH) {
            float acc = pb2[j];
            #pragma unroll 8
            for (int k = 0; k < HH; k++) acc += lb1[k] * pw2[k * HH + j];
            g_b1p[j] = acc;
        } else if (j < HH + CO) {
            int c = j - HH;
            float acc = clsb[c];
            #pragma unroll 8
            for (int k = 0; k < HH; k++) acc += lb2[k] * clsw[k * CO + c];
            g_b2p[c] = acc;
        }
        return;
    }

    extern __shared__ float sm[];
    float* AS = sm;
    float* BS = sm + 4 * A_TILE_F;

    const int tid   = threadIdx.x;
    const int r0    = blockIdx.x * 128;
    const int wid   = tid >> 5;
    const int lane  = tid & 31;
    const int grp   = lane >> 2;
    const int qid   = lane & 3;
    const int warpM = wid & 1;
    const int warpN = wid >> 1;
    const int M = HH;

    float acc[4][4][4];
    #pragma unroll
    for (int mi = 0; mi < 4; mi++)
        #pragma unroll
        for (int ni = 0; ni < 4; ni++)
            #pragma unroll
            for (int r = 0; r < 4; r++) acc[mi][ni][r] = 0.0f;

    const int nt = K >> 4;

    auto issue = [&](int t, int stg) {
        int k0 = t << 4;
        float* as = AS + stg * A_TILE_F;
        float* bs = BS + stg * B_TILE_F;
        #pragma unroll
        for (int i = 0; i < 2; i++) {
            int idx = tid + i * 256;
            int row = idx >> 2, kc = (idx & 3) << 2;
            int gr  = r0 + row;
            cp16((uint32_t)__cvta_generic_to_shared(as + row * 20 + kc),
                 A + (size_t)gr * K + k0 + kc, gr < Nrows);
        }
        #pragma unroll
        for (int i = 0; i < 2; i++) {
            int idx = tid + i * 256;
            int kr = idx >> 5, col = (idx & 31) << 2;
            cp16((uint32_t)__cvta_generic_to_shared(bs + kr * 136 + col),
                 B + (size_t)(k0 + kr) * M + col, true);
        }
        CP_COMMIT();
    };

    int npre = (nt < 3) ? nt : 3;
    for (int t = 0; t < npre; t++) issue(t, t);

    for (int t = 0; t < nt; t++) {
        CP_WAIT(2);
        __syncthreads();
        int tn = t + 3;
        if (tn < nt) issue(tn, tn & 3);

        const float* as = AS + (t & 3) * A_TILE_F;
        const float* bs = BS + (t & 3) * B_TILE_F;
        #pragma unroll
        for (int ks = 0; ks < 16; ks += 8) {
            uint32_t af[4][4], bf[4][2];
            #pragma unroll
            for (int mi = 0; mi < 4; mi++) {
                int m = warpM * 64 + mi * 16 + grp;
                af[mi][0] = ldtf(as[(m    ) * 20 + ks + qid]);
                af[mi][1] = ldtf(as[(m + 8) * 20 + ks + qid]);
                af[mi][2] = ldtf(as[(m    ) * 20 + ks + qid + 4]);
                af[mi][3] = ldtf(as[(m + 8) * 20 + ks + qid + 4]);
            }
            #pragma unroll
            for (int ni = 0; ni < 4; ni++) {
                int n = warpN * 32 + ni * 8 + grp;
                bf[ni][0] = ldtf(bs[(ks + qid    ) * 136 + n]);
                bf[ni][1] = ldtf(bs[(ks + qid + 4) * 136 + n]);
            }
            #pragma unroll
            for (int mi = 0; mi < 4; mi++)
                #pragma unroll
                for (int ni = 0; ni < 4; ni++)
                    MMA_TF32(acc[mi][ni], af[mi], bf[ni]);
        }
    }

    #pragma unroll
    for (int mi = 0; mi < 4; mi++) {
        #pragma unroll
        for (int half = 0; half < 2; half++) {
            int row = r0 + warpM * 64 + mi * 16 + grp + half * 8;
            if (row >= Nrows) continue;
            #pragma unroll
            for (int ni = 0; ni < 4; ni++) {
                int col = warpN * 32 + ni * 8 + qid * 2;
                size_t off = (size_t)row * M + col;
                float vx = acc[mi][ni][half * 2 + 0] + bias[col];
                float vy = acc[mi][ni][half * 2 + 1] + bias[col + 1];
                *(float2*)&C[off] = make_float2(vx, vy);
            }
        }
    }
}

// ---------------- cell megakernel, 2-stage cp.async, phase-overlapped ----------------
#define SMEM_MEGA ((2 * A_TILE_F + 2 * B_TILE_F + 128 * 136) * 4)

template<int CLS>
__global__ __launch_bounds__(256)
void cell_post_kernel(const float* __restrict__ xh, const float* __restrict__ tx1,
                      const float* __restrict__ s,
                      const float* __restrict__ cw0, const float* __restrict__ cw1,
                      const float* __restrict__ cb,
                      const float* __restrict__ sw, const float* __restrict__ sb,
                      const float* __restrict__ lwp, const float* __restrict__ lbp,
                      float* __restrict__ out, int Nrows) {
    extern __shared__ float sm[];
    float* AS = sm;
    float* BS = sm + 2 * A_TILE_F;
    float* T  = sm + 2 * A_TILE_F + 2 * B_TILE_F;

    const int tid   = threadIdx.x;
    const int r0    = blockIdx.x * 128;
    const int wid   = tid >> 5;
    const int lane  = tid & 31;
    const int grp   = lane >> 2;
    const int qid   = lane & 3;
    const int warpM = wid & 1;
    const int warpN = wid >> 1;
    const int BSTRIDE = CLS ? CO : HH;

    float acc[4][4][4];

    auto zero_acc = [&]() {
        #pragma unroll
        for (int mi = 0; mi < 4; mi++)
            #pragma unroll
            for (int ni = 0; ni < 4; ni++)
                #pragma unroll
                for (int r = 0; r < 4; r++) acc[mi][ni][r] = 0.0f;
    };

    auto issue_ab = [&](const float* __restrict__ A, const float* __restrict__ B,
                        int k0, int stg) {
        float* as = AS + stg * A_TILE_F;
        float* bs = BS + stg * B_TILE_F;
        #pragma unroll
        for (int i = 0; i < 2; i++) {
            int idx = tid + i * 256;
            int row = idx >> 2, kc = (idx & 3) << 2;
            int gr  = r0 + row;
            cp16((uint32_t)__cvta_generic_to_shared(as + row * 20 + kc),
                 A + (size_t)gr * HH + k0 + kc, gr < Nrows);
        }
        #pragma unroll
        for (int i = 0; i < 2; i++) {
            int idx = tid + i * 256;
            int kr = idx >> 5, col = (idx & 31) << 2;
            cp16((uint32_t)__cvta_generic_to_shared(bs + kr * 136 + col),
                 B + (size_t)(k0 + kr) * HH + col, true);
        }
        CP_COMMIT();
    };

    auto issue_bc = [&](const float* __restrict__ B, int k0, int stg) {
        float* bs = BS + stg * B_TILE_F;
        #pragma unroll
        for (int i = 0; i < 2; i++) {
            int idx = tid + i * 256;
            int kr = idx >> 5, col = (idx & 31) << 2;
            cp16((uint32_t)__cvta_generic_to_shared(bs + kr * 136 + col),
                 B + (size_t)(k0 + kr) * BSTRIDE + col, col < BSTRIDE);
        }
        CP_COMMIT();
    };

    auto compute_s = [&](const float* __restrict__ as, const float* __restrict__ bs) {
        #pragma unroll
        for (int ks = 0; ks < 16; ks += 8) {
            uint32_t af[4][4], bf[4][2];
            #pragma unroll
            for (int mi = 0; mi < 4; mi++) {
                int m = warpM * 64 + mi * 16 + grp;
                af[mi][0] = ldtf(as[(m    ) * 20 + ks + qid]);
                af[mi][1] = ldtf(as[(m + 8) * 20 + ks + qid]);
                af[mi][2] = ldtf(as[(m    ) * 20 + ks + qid + 4]);
                af[mi][3] = ldtf(as[(m + 8) * 20 + ks + qid + 4]);
            }
            #pragma unroll
            for (int ni = 0; ni < 4; ni++) {
                int n = warpN * 32 + ni * 8 + grp;
                bf[ni][0] = ldtf(bs[(ks + qid    ) * 136 + n]);
                bf[ni][1] = ldtf(bs[(ks + qid + 4) * 136 + n]);
            }
            #pragma unroll
            for (int mi = 0; mi < 4; mi++)
                #pragma unroll
                for (int ni = 0; ni < 4; ni++)
                    MMA_TF32(acc[mi][ni], af[mi], bf[ni]);
        }
    };

    auto compute_t = [&](const float* __restrict__ at, const float* __restrict__ bs) {
        #pragma unroll
        for (int ks = 0; ks < 16; ks += 8) {
            uint32_t af[4][4], bf[4][2];
            #pragma unroll
            for (int mi = 0; mi < 4; mi++) {
                int m = warpM * 64 + mi * 16 + grp;
                af[mi][0] = ldtf(at[(ks + qid    ) * 136 + m]);
                af[mi][1] = ldtf(at[(ks + qid    ) * 136 + m + 8]);
                af[mi][2] = ldtf(at[(ks + qid + 4) * 136 + m]);
                af[mi][3] = ldtf(at[(ks + qid + 4) * 136 + m + 8]);
            }
            #pragma unroll
            for (int ni = 0; ni < 4; ni++) {
                int n = warpN * 32 + ni * 8 + grp;
                bf[ni][0] = ldtf(bs[(ks + qid    ) * 136 + n]);
                bf[ni][1] = ldtf(bs[(ks + qid + 4) * 136 + n]);
            }
            #pragma unroll
            for (int mi = 0; mi < 4; mi++)
                #pragma unroll
                for (int ni = 0; ni < 4; ni++)
                    MMA_TF32(acc[mi][ni], af[mi], bf[ni]);
        }
    };

    // ---- Phase A: 16 virtual tiles (xh/cw0 then tx1/cw1) ----
    zero_acc();
    issue_ab(xh, cw0, 0, 0);
    #pragma unroll 1
    for (int t = 0; t < 16; t++) {
        CP_WAIT(0);
        __syncthreads();
        int tn = t + 1;
        if (tn < 16) {
            const float* An = (tn < 8) ? xh  : tx1;
            const float* Bn = (tn < 8) ? cw0 : cw1;
            issue_ab(An, Bn, (tn & 7) << 4, tn & 1);
        }
        compute_s(AS + (t & 1) * A_TILE_F, BS + (t & 1) * B_TILE_F);
    }
    issue_ab(s, sw, 0, 0);   // pre-issue phase-B tile 0
    #pragma unroll
    for (int mi = 0; mi < 4; mi++)
        #pragma unroll
        for (int half = 0; half < 2; half++) {
            int rl = warpM * 64 + mi * 16 + grp + half * 8;
            #pragma unroll
            for (int ni = 0; ni < 4; ni++) {
                int col = warpN * 32 + ni * 8 + qid * 2;
                float vx = acc[mi][ni][half*2+0] + cb[col];
                float vy = acc[mi][ni][half*2+1] + cb[col+1];
                vx = (vx > 0.f) ? vx : 0.01f * vx;
                vy = (vy > 0.f) ? vy : 0.01f * vy;
                T[(col  ) * 136 + rl] = vx;
                T[(col+1) * 136 + rl] = vy;
            }
        }

    // ---- Phase B: 8 tiles of s@sw ----
    zero_acc();
    #pragma unroll 1
    for (int t = 0; t < 8; t++) {
        CP_WAIT(0);
        __syncthreads();
        if (t + 1 < 8) issue_ab(s, sw, (t + 1) << 4, (t + 1) & 1);
        compute_s(AS + (t & 1) * A_TILE_F, BS + (t & 1) * B_TILE_F);
    }
    issue_bc(lwp, 0, 0);     // pre-issue phase-C weight tile 0
    #pragma unroll
    for (int mi = 0; mi < 4; mi++)
        #pragma unroll
        for (int half = 0; half < 2; half++) {
            int rl = warpM * 64 + mi * 16 + grp + half * 8;
            #pragma unroll
            for (int ni = 0; ni < 4; ni++) {
                int col = warpN * 32 + ni * 8 + qid * 2;
                float vx = acc[mi][ni][half*2+0] + sb[col];
                float vy = acc[mi][ni][half*2+1] + sb[col+1];
                vx = (vx > 0.f) ? vx : 0.01f * vx;
                vy = (vy > 0.f) ? vy : 0.01f * vy;
                T[(col  ) * 136 + rl] += vx;
                T[(col+1) * 136 + rl] += vy;
            }
        }
    __syncthreads();

    // ---- Phase C: 8 tiles of T@W' ----
    zero_acc();
    #pragma unroll 1
    for (int t = 0; t < 8; t++) {
        CP_WAIT(0);
        __syncthreads();
        if (t + 1 < 8) issue_bc(lwp, (t + 1) << 4, (t + 1) & 1);
        compute_t(T + t * 16 * 136, BS + (t & 1) * B_TILE_F);
    }

    if (CLS == 0) {
        #pragma unroll
        for (int mi = 0; mi < 4; mi++)
            #pragma unroll
            for (int half = 0; half < 2; half++) {
                int row = r0 + warpM * 64 + mi * 16 + grp + half * 8;
                if (row >= Nrows) continue;
                #pragma unroll
                for (int ni = 0; ni < 4; ni++) {
                    int col = warpN * 32 + ni * 8 + qid * 2;
                    float vx = acc[mi][ni][half*2+0] + lbp[col];
                    float vy = acc[mi][ni][half*2+1] + lbp[col+1];
                    *(float2*)&out[(size_t)row * HH + col] = make_float2(vx, vy);
                }
            }
    } else {
        __syncthreads();
        float* L = sm;                // [128][44]
        #pragma unroll
        for (int mi = 0; mi < 4; mi++)
            #pragma unroll
            for (int half = 0; half < 2; half++) {
                int rl = warpM * 64 + mi * 16 + grp + half * 8;
                #pragma unroll
                for (int ni = 0; ni < 4; ni++) {
                    int col = warpN * 32 + ni * 8 + qid * 2;
                    if (col >= CO) continue;
                    L[rl * 44 + col    ] = acc[mi][ni][half*2+0] + lbp[col];
                    L[rl * 44 + col + 1] = acc[mi][ni][half*2+1] + lbp[col+1];
                }
            }
        __syncthreads();
        for (int r = 0; r < 16; r++) {
            int rl  = wid * 16 + r;
            int row = r0 + rl;
            if (row >= Nrows) break;
            float v0 = L[rl * 44 + lane];
            float v1 = (lane < CO - 32) ? L[rl * 44 + 32 + lane] : -3.4e38f;
            float m = fmaxf(v0, v1);
            #pragma unroll
            for (int o = 16; o > 0; o >>= 1) m = fmaxf(m, __shfl_xor_sync(0xffffffffu, m, o));
            float e = expf(v0 - m) + ((lane < CO - 32) ? expf(v1 - m) : 0.0f);
            #pragma unroll
            for (int o = 16; o > 0; o >>= 1) e += __shfl_xor_sync(0xffffffffu, e, o);
            float ls = m + logf(e);
            out[(size_t)row * CO + lane] = v0 - ls;
            if (lane < CO - 32) out[(size_t)row * CO + 32 + lane] = v1 - ls;
        }
    }
}

// ---------------- launch ----------------
extern "C" void kernel_launch(void* const* d_in, const int* in_sizes, int n_in,
                              void* d_out, int out_size) {
    const float* x    = (const float*)d_in[0];
    const int*   ei   = (const int*)  d_in[1];
    const float* w    = (const float*)d_in[2];
    const float* pre_w1 = (const float*)d_in[3];
    const float* pre_b1 = (const float*)d_in[4];
    const float* cw0_1  = (const float*)d_in[5];
    const float* cw1_1  = (const float*)d_in[6];
    const float* cb_1   = (const float*)d_in[7];
    const float* sw_1   = (const float*)d_in[8];
    const float* sb_1   = (const float*)d_in[9];
    const float* lw_1   = (const float*)d_in[10];
    const float* lb_1   = (const float*)d_in[11];
    const float* pre_w2 = (const float*)d_in[12];
    const float* pre_b2 = (const float*)d_in[13];
    const float* cw0_2  = (const float*)d_in[14];
    const float* cw1_2  = (const float*)d_in[15];
    const float* cb_2   = (const float*)d_in[16];
    const float* sw_2   = (const float*)d_in[17];
    const float* sb_2   = (const float*)d_in[18];
    const float* lw_2   = (const float*)d_in[19];
    const float* lb_2   = (const float*)d_in[20];
    const float* cls_w  = (const float*)d_in[21];
    const float* cls_b  = (const float*)d_in[22];
    float* out = (float*)d_out;

    void *p_xh, *p_tx1, *p_s, *p_xc, *p_w1p, *p_b1p, *p_w2p, *p_b2p;
    cudaGetSymbolAddress(&p_xh,  g_xh);
    cudaGetSymbolAddress(&p_tx1, g_tx1);
    cudaGetSymbolAddress(&p_s,   g_s);
    cudaGetSymbolAddress(&p_xc,  g_xc);
    cudaGetSymbolAddress(&p_w1p, g_w1p);
    cudaGetSymbolAddress(&p_b1p, g_b1p);
    cudaGetSymbolAddress(&p_w2p, g_w2p);
    cudaGetSymbolAddress(&p_b2p, g_b2p);
    float* xh  = (float*)p_xh;
    float* tx1 = (float*)p_tx1;
    float* s   = (float*)p_s;
    float* xc  = (float*)p_xc;
    float* w1p = (float*)p_w1p;
    float* b1p = (float*)p_b1p;
    float* w2p = (float*)p_w2p;
    float* b2p = (float*)p_b2p;

    static bool attr_done = false;
    if (!attr_done) {
        cudaFuncSetAttribute(cell_post_kernel<0>,
                             cudaFuncAttributeMaxDynamicSharedMemorySize, SMEM_MEGA);
        cudaFuncSetAttribute(cell_post_kernel<1>,
                             cudaFuncAttributeMaxDynamicSharedMemorySize, SMEM_MEGA);
        cudaFuncSetAttribute(gemm_pre_zero_kernel,
                             cudaFuncAttributeMaxDynamicSharedMemorySize, SMEM_GEMM);
        attr_done = true;
    }

    // 1: gemm + zero + fuse_w + fuse_bias (all independent tails)
    gemm_pre_zero_kernel<<<GB_TOTAL, 256, SMEM_GEMM>>>(
        x, pre_w1, pre_b1, xh, NN, FIN,
        lw_1, pre_w2, lw_2, cls_w, lb_1, pre_b2, lb_2, cls_b);
    // 2: edge histogram / degree
    prep_edge_kernel<<<(NE + 255)/256, 256>>>(ei, w);
    // 3: scan block sums
    scan1_kernel<<<160, 256>>>();
    // 4: rowptr emit + node prep
    scan3m_kernel<<<160, 256>>>();
    // 5: CSR fill
    fill_kernel<<<(NE + 255)/256, 256>>>(ei, w);
    // 6: aggregate (cell 1)
    aggregate_kernel<<<(NN * 64 + 255) / 256, 256>>>((const float2*)xh, (float2*)tx1, (float2*)s);
    // 7: cell 1 post (emits cell-2's xh via W1')
    cell_post_kernel<0><<<GB_GEMM, 256, SMEM_MEGA>>>(xh, tx1, s, cw0_1, cw1_1, cb_1,
                                                     sw_1, sb_1, w1p, b1p, xc, NN);
    // 8: aggregate (cell 2)
    aggregate_kernel<<<(NN * 64 + 255) / 256, 256>>>((const float2*)xc, (float2*)tx1, (float2*)s);
    // 9: cell 2 post (emits logits + log_softmax)
    cell_post_kernel<1><<<GB_GEMM, 256, SMEM_MEGA>>>(xc, tx1, s, cw0_2, cw1_2, cb_2,
                                                     sw_2, sb_2, w2p, b2p, out, NN);
}

// round 15
// speedup vs baseline: 1.1641x; 1.1641x over previous
#include <cuda_runtime.h>
#include <cuda_bf16.h>
#include <math.h>
#include <stdint.h>

#define NN   40000
#define NE   640000
#define FIN  512
#define HH   128
#define CO   40
#define GB_GEMM  313                  // gemm blocks
#define GB_ZERO  ((NN + 255) / 256)   // 157 zero blocks
#define GB_FUSEW ((HH*HH + HH*CO) / 256)  // 84 fuse_w blocks
#define GB_TOTAL (GB_GEMM + GB_ZERO + GB_FUSEW + 1)

// ---------------- scratch (device globals) ----------------
__device__ __align__(16) float g_xh [NN*HH];
__device__ __align__(16) float g_tx1[NN*HH];
__device__ __align__(16) float g_s  [NN*HH];
__device__ __align__(16) float g_xc [NN*HH];
__device__ __align__(16) float g_w1p[HH*HH];   // lw1 @ pw2
__device__ __align__(16) float g_b1p[HH];      // lb1 @ pw2 + pb2
__device__ __align__(16) float g_w2p[HH*CO];   // lw2 @ cls_w
__device__ __align__(16) float g_b2p[CO];      // lb2 @ cls_w + cls_b
__device__ float g_deg   [NN];
__device__ float g_dis   [NN];
__device__ float g_loopw [NN];
__device__ float g_invcnt[NN];
__device__ __align__(16) int g_cnt   [NN + 64];
__device__ int   g_cursor[NN];
__device__ int   g_rowptr[NN + 1];
__device__ int   g_bsum  [160];
__device__ __align__(16) int4 g_emeta[NE];

// ---------------- graph prep ----------------
__global__ void prep_edge_kernel(const int* __restrict__ ei, const float* __restrict__ w) {
    int e = blockIdx.x * blockDim.x + threadIdx.x;
    if (e >= NE) return;
    int s = ei[e], d = ei[NE + e];
    float we = w[e];
    if (s != d) {
        atomicAdd(&g_deg[s], we);
        atomicAdd(&g_cnt[d], 1);
    } else {
        g_loopw[s] = we;
    }
}

// ---------------- scan phase 1: block sums ----------------
__global__ __launch_bounds__(256)
void scan1_kernel() {
    __shared__ int swarp[8];
    int idx = blockIdx.x * 256 + threadIdx.x;
    int lane = threadIdx.x & 31, wid = threadIdx.x >> 5;
    int v = (idx < NN) ? g_cnt[idx] : 0;
    int sum = v;
    #pragma unroll
    for (int o = 16; o > 0; o >>= 1) sum += __shfl_xor_sync(0xffffffffu, sum, o);
    if (lane == 0) swarp[wid] = sum;
    __syncthreads();
    if (threadIdx.x == 0) {
        int t = 0;
        #pragma unroll
        for (int i = 0; i < 8; i++) t += swarp[i];
        g_bsum[blockIdx.x] = t;
    }
}

// ---------------- scan phase 2 (merged): rowptr emit + node prep ----------------
__global__ __launch_bounds__(256)
void scan3m_kernel() {
    __shared__ int swarp[8];
    __shared__ int s_off;
    int tidx = threadIdx.x;
    int lane = tidx & 31, wid = tidx >> 5;

    if (wid == 0) {
        int acc = 0;
        for (int i = lane; i < blockIdx.x; i += 32) acc += g_bsum[i];
        #pragma unroll
        for (int o = 16; o > 0; o >>= 1) acc += __shfl_xor_sync(0xffffffffu, acc, o);
        if (lane == 0) s_off = acc;
    }

    int idx = blockIdx.x * 256 + tidx;
    int v = (idx < NN) ? g_cnt[idx] : 0;
    int incl = v;
    #pragma unroll
    for (int o = 1; o < 32; o <<= 1) {
        int u = __shfl_up_sync(0xffffffffu, incl, o);
        if (lane >= o) incl += u;
    }
    if (lane == 31) swarp[wid] = incl;
    __syncthreads();
    if (wid == 0 && lane < 8) {
        int x = swarp[lane];
        int ix = x;
        #pragma unroll
        for (int o = 1; o < 8; o <<= 1) {
            int u = __shfl_up_sync(0xffu, ix, o);
            if (lane >= o) ix += u;
        }
        swarp[lane] = ix - x;
    }
    __syncthreads();
    int excl = s_off + swarp[wid] + incl - v;
    if (idx < NN) {
        g_rowptr[idx] = excl;
        float dg = g_deg[idx];
        g_dis[idx]    = (dg > 0.0f) ? rsqrtf(dg) : 0.0f;
        g_invcnt[idx] = 1.0f / ((float)v + 1.0f);
    }
    if (idx == NN - 1) g_rowptr[NN] = excl + v;
}

// ---------------- fill CSR ----------------
__global__ void fill_kernel(const int* __restrict__ ei, const float* __restrict__ w) {
    int e = blockIdx.x * blockDim.x + threadIdx.x;
    if (e >= NE) return;
    int s = ei[e], d = ei[NE + e];
    if (s == d) return;
    float we   = w[e];
    float coef = -g_dis[s] * we * g_dis[d];
    int pos = g_rowptr[d] + atomicAdd(&g_cursor[d], 1);
    g_emeta[pos] = make_int4(s, __float_as_int(we), __float_as_int(coef), 0);
}

// ---------------- CSR gather-reduce: warp per node, meta-prefetch (R13 shape) ----------------
__global__ __launch_bounds__(256)
void aggregate_kernel(const float4* __restrict__ xh,
                      float4* __restrict__ tx1, float4* __restrict__ s) {
    int n    = (blockIdx.x * blockDim.x + threadIdx.x) >> 5;
    int lane = threadIdx.x & 31;
    if (n >= NN) return;
    int beg = g_rowptr[n], end = g_rowptr[n + 1];

    float lw = g_loopw[n];
    float4 xv = xh[n * 32 + lane];
    float4 a = make_float4(0.f, 0.f, 0.f, 0.f);
    float4 b = make_float4(lw * xv.x, lw * xv.y, lw * xv.z, lw * xv.w);

    int end4 = beg + ((end - beg) & ~3);
    int e = beg;
    if (e < end4) {
        int4 m0 = g_emeta[e+0], m1 = g_emeta[e+1], m2 = g_emeta[e+2], m3 = g_emeta[e+3];
        for (; e < end4; ) {
            float4 v0 = xh[m0.x * 32 + lane];
            float4 v1 = xh[m1.x * 32 + lane];
            float4 v2 = xh[m2.x * 32 + lane];
            float4 v3 = xh[m3.x * 32 + lane];
            float w0 = __int_as_float(m0.y), c0 = __int_as_float(m0.z);
            float w1 = __int_as_float(m1.y), c1 = __int_as_float(m1.z);
            float w2 = __int_as_float(m2.y), c2 = __int_as_float(m2.z);
            float w3 = __int_as_float(m3.y), c3 = __int_as_float(m3.z);
            e += 4;
            if (e < end4) {
                m0 = g_emeta[e+0]; m1 = g_emeta[e+1];
                m2 = g_emeta[e+2]; m3 = g_emeta[e+3];
            }
            a.x += c0*v0.x + c1*v1.x + c2*v2.x + c3*v3.x;
            a.y += c0*v0.y + c1*v1.y + c2*v2.y + c3*v3.y;
            a.z += c0*v0.z + c1*v1.z + c2*v2.z + c3*v3.z;
            a.w += c0*v0.w + c1*v1.w + c2*v2.w + c3*v3.w;
            b.x += w0*v0.x + w1*v1.x + w2*v2.x + w3*v3.x;
            b.y += w0*v0.y + w1*v1.y + w2*v2.y + w3*v3.y;
            b.z += w0*v0.z + w1*v1.z + w2*v2.z + w3*v3.z;
            b.w += w0*v0.w + w1*v1.w + w2*v2.w + w3*v3.w;
        }
    }
    for (; e < end; e++) {
        int4 m = g_emeta[e];
        float we = __int_as_float(m.y);
        float cf = __int_as_float(m.z);
        float4 v = xh[m.x * 32 + lane];
        a.x += cf * v.x; a.y += cf * v.y; a.z += cf * v.z; a.w += cf * v.w;
        b.x += we * v.x; b.y += we * v.y; b.z += we * v.z; b.w += we * v.w;
    }
    float ic = g_invcnt[n];
    tx1[n * 32 + lane] = a;
    s  [n * 32 + lane] = make_float4(b.x * ic, b.y * ic, b.z * ic, b.w * ic);
}

// ---------------- common GEMM helpers ----------------
__device__ __forceinline__ void cp16(uint32_t dst, const void* src, bool valid) {
    int sz = valid ? 16 : 0;
    asm volatile("cp.async.cg.shared.global [%0], [%1], 16, %2;"
                 :: "r"(dst), "l"(src), "r"(sz));
}
#define CP_COMMIT() asm volatile("cp.async.commit_group;")
#define CP_WAIT(N)  asm volatile("cp.async.wait_group %0;" :: "n"(N))

__device__ __forceinline__ uint32_t ldtf(float x) {
    uint32_t u;
    asm("cvt.rna.tf32.f32 %0, %1;" : "=r"(u) : "f"(x));
    return u;
}

#define MMA_TF32(acc, af, bf)                                                   \
    asm volatile(                                                               \
        "mma.sync.aligned.m16n8k8.row.col.f32.tf32.tf32.f32 "                   \
        "{%0,%1,%2,%3}, {%4,%5,%6,%7}, {%8,%9}, {%0,%1,%2,%3};"                 \
        : "+f"((acc)[0]), "+f"((acc)[1]), "+f"((acc)[2]), "+f"((acc)[3])        \
        : "r"((af)[0]), "r"((af)[1]), "r"((af)[2]), "r"((af)[3]),               \
          "r"((bf)[0]), "r"((bf)[1]))

#define A_TILE_F (128 * 20)
#define B_TILE_F (16 * 136)

// ---------------- cell-1 pre-GEMM fused with zero + fuse_w + fuse_bias tails ----------------
#define SMEM_GEMM ((4 * A_TILE_F + 4 * B_TILE_F) * 4)

__global__ __launch_bounds__(256)
void gemm_pre_zero_kernel(const float* __restrict__ A, const float* __restrict__ B,
                          const float* __restrict__ bias, float* __restrict__ C,
                          int Nrows, int K,
                          const float* __restrict__ lw1, const float* __restrict__ pw2,
                          const float* __restrict__ lw2, const float* __restrict__ clsw,
                          const float* __restrict__ lb1, const float* __restrict__ pb2,
                          const float* __restrict__ lb2, const float* __restrict__ clsb) {
    // tail region 1: zero graph-prep buffers
    if (blockIdx.x >= GB_GEMM && blockIdx.x < GB_GEMM + GB_ZERO) {
        int n = (blockIdx.x - GB_GEMM) * 256 + threadIdx.x;
        if (n < NN) { g_deg[n] = 0.0f; g_loopw[n] = 1.0f; g_cnt[n] = 0; g_cursor[n] = 0; }
        return;
    }
    // tail region 2: fuse_w  (lw1@pw2 then lw2@cls_w)
    if (blockIdx.x >= GB_GEMM + GB_ZERO && blockIdx.x < GB_GEMM + GB_ZERO + GB_FUSEW) {
        int idx = (blockIdx.x - GB_GEMM - GB_ZERO) * 256 + threadIdx.x;
        if (idx < HH * HH) {
            int r = idx / HH, c = idx % HH;
            float acc = 0.0f;
            #pragma unroll 8
            for (int k = 0; k < HH; k++) acc += lw1[r * HH + k] * pw2[k * HH + c];
            g_w1p[idx] = acc;
        } else if (idx < HH * HH + HH * CO) {
            int t = idx - HH * HH;
            int r = t / CO, c = t % CO;
            float acc = 0.0f;
            #pragma unroll 8
            for (int k = 0; k < HH; k++) acc += lw2[r * HH + k] * clsw[k * CO + c];
            g_w2p[t] = acc;
        }
        return;
    }
    // tail region 3: fuse_bias
    if (blockIdx.x == GB_GEMM + GB_ZERO + GB_FUSEW) {
        int j = threadIdx.x;
        if (j < HH) {
            float acc = pb2[j];
            #pragma unroll 8
            for (int k = 0; k < HH; k++) acc += lb1[k] * pw2[k * HH + j];
            g_b1p[j] = acc;
        } else if (j < HH + CO) {
            int c = j - HH;
            float acc = clsb[c];
            #pragma unroll 8
            for (int k = 0; k < HH; k++) acc += lb2[k] * clsw[k * CO + c];
            g_b2p[c] = acc;
        }
        return;
    }

    extern __shared__ float sm[];
    float* AS = sm;
    float* BS = sm + 4 * A_TILE_F;

    const int tid   = threadIdx.x;
    const int r0    = blockIdx.x * 128;
    const int wid   = tid >> 5;
    const int lane  = tid & 31;
    const int grp   = lane >> 2;
    const int qid   = lane & 3;
    const int warpM = wid & 1;
    const int warpN = wid >> 1;
    const int M = HH;

    float acc[4][4][4];
    #pragma unroll
    for (int mi = 0; mi < 4; mi++)
        #pragma unroll
        for (int ni = 0; ni < 4; ni++)
            #pragma unroll
            for (int r = 0; r < 4; r++) acc[mi][ni][r] = 0.0f;

    const int nt = K >> 4;

    auto issue = [&](int t, int stg) {
        int k0 = t << 4;
        float* as = AS + stg * A_TILE_F;
        float* bs = BS + stg * B_TILE_F;
        #pragma unroll
        for (int i = 0; i < 2; i++) {
            int idx = tid + i * 256;
            int row = idx >> 2, kc = (idx & 3) << 2;
            int gr  = r0 + row;
            cp16((uint32_t)__cvta_generic_to_shared(as + row * 20 + kc),
                 A + (size_t)gr * K + k0 + kc, gr < Nrows);
        }
        #pragma unroll
        for (int i = 0; i < 2; i++) {
            int idx = tid + i * 256;
            int kr = idx >> 5, col = (idx & 31) << 2;
            cp16((uint32_t)__cvta_generic_to_shared(bs + kr * 136 + col),
                 B + (size_t)(k0 + kr) * M + col, true);
        }
        CP_COMMIT();
    };

    int npre = (nt < 3) ? nt : 3;
    for (int t = 0; t < npre; t++) issue(t, t);

    for (int t = 0; t < nt; t++) {
        CP_WAIT(2);
        __syncthreads();
        int tn = t + 3;
        if (tn < nt) issue(tn, tn & 3);

        const float* as = AS + (t & 3) * A_TILE_F;
        const float* bs = BS + (t & 3) * B_TILE_F;
        #pragma unroll
        for (int ks = 0; ks < 16; ks += 8) {
            uint32_t af[4][4], bf[4][2];
            #pragma unroll
            for (int mi = 0; mi < 4; mi++) {
                int m = warpM * 64 + mi * 16 + grp;
                af[mi][0] = ldtf(as[(m    ) * 20 + ks + qid]);
                af[mi][1] = ldtf(as[(m + 8) * 20 + ks + qid]);
                af[mi][2] = ldtf(as[(m    ) * 20 + ks + qid + 4]);
                af[mi][3] = ldtf(as[(m + 8) * 20 + ks + qid + 4]);
            }
            #pragma unroll
            for (int ni = 0; ni < 4; ni++) {
                int n = warpN * 32 + ni * 8 + grp;
                bf[ni][0] = ldtf(bs[(ks + qid    ) * 136 + n]);
                bf[ni][1] = ldtf(bs[(ks + qid + 4) * 136 + n]);
            }
            #pragma unroll
            for (int mi = 0; mi < 4; mi++)
                #pragma unroll
                for (int ni = 0; ni < 4; ni++)
                    MMA_TF32(acc[mi][ni], af[mi], bf[ni]);
        }
    }

    #pragma unroll
    for (int mi = 0; mi < 4; mi++) {
        #pragma unroll
        for (int half = 0; half < 2; half++) {
            int row = r0 + warpM * 64 + mi * 16 + grp + half * 8;
            if (row >= Nrows) continue;
            #pragma unroll
            for (int ni = 0; ni < 4; ni++) {
                int col = warpN * 32 + ni * 8 + qid * 2;
                size_t off = (size_t)row * M + col;
                float vx = acc[mi][ni][half * 2 + 0] + bias[col];
                float vy = acc[mi][ni][half * 2 + 1] + bias[col + 1];
                *(float2*)&C[off] = make_float2(vx, vy);
            }
        }
    }
}

// ---------------- cell megakernel, 2-stage cp.async, phase-overlapped ----------------
#define SMEM_MEGA ((2 * A_TILE_F + 2 * B_TILE_F + 128 * 136) * 4)

template<int CLS>
__global__ __launch_bounds__(256)
void cell_post_kernel(const float* __restrict__ xh, const float* __restrict__ tx1,
                      const float* __restrict__ s,
                      const float* __restrict__ cw0, const float* __restrict__ cw1,
                      const float* __restrict__ cb,
                      const float* __restrict__ sw, const float* __restrict__ sb,
                      const float* __restrict__ lwp, const float* __restrict__ lbp,
                      float* __restrict__ out, int Nrows) {
    extern __shared__ float sm[];
    float* AS = sm;
    float* BS = sm + 2 * A_TILE_F;
    float* T  = sm + 2 * A_TILE_F + 2 * B_TILE_F;

    const int tid   = threadIdx.x;
    const int r0    = blockIdx.x * 128;
    const int wid   = tid >> 5;
    const int lane  = tid & 31;
    const int grp   = lane >> 2;
    const int qid   = lane & 3;
    const int warpM = wid & 1;
    const int warpN = wid >> 1;
    const int BSTRIDE = CLS ? CO : HH;

    float acc[4][4][4];

    auto zero_acc = [&]() {
        #pragma unroll
        for (int mi = 0; mi < 4; mi++)
            #pragma unroll
            for (int ni = 0; ni < 4; ni++)
                #pragma unroll
                for (int r = 0; r < 4; r++) acc[mi][ni][r] = 0.0f;
    };

    auto issue_ab = [&](const float* __restrict__ A, const float* __restrict__ B,
                        int k0, int stg) {
        float* as = AS + stg * A_TILE_F;
        float* bs = BS + stg * B_TILE_F;
        #pragma unroll
        for (int i = 0; i < 2; i++) {
            int idx = tid + i * 256;
            int row = idx >> 2, kc = (idx & 3) << 2;
            int gr  = r0 + row;
            cp16((uint32_t)__cvta_generic_to_shared(as + row * 20 + kc),
                 A + (size_t)gr * HH + k0 + kc, gr < Nrows);
        }
        #pragma unroll
        for (int i = 0; i < 2; i++) {
            int idx = tid + i * 256;
            int kr = idx >> 5, col = (idx & 31) << 2;
            cp16((uint32_t)__cvta_generic_to_shared(bs + kr * 136 + col),
                 B + (size_t)(k0 + kr) * HH + col, true);
        }
        CP_COMMIT();
    };

    auto issue_bc = [&](const float* __restrict__ B, int k0, int stg) {
        float* bs = BS + stg * B_TILE_F;
        #pragma unroll
        for (int i = 0; i < 2; i++) {
            int idx = tid + i * 256;
            int kr = idx >> 5, col = (idx & 31) << 2;
            cp16((uint32_t)__cvta_generic_to_shared(bs + kr * 136 + col),
                 B + (size_t)(k0 + kr) * BSTRIDE + col, col < BSTRIDE);
        }
        CP_COMMIT();
    };

    auto compute_s = [&](const float* __restrict__ as, const float* __restrict__ bs) {
        #pragma unroll
        for (int ks = 0; ks < 16; ks += 8) {
            uint32_t af[4][4], bf[4][2];
            #pragma unroll
            for (int mi = 0; mi < 4; mi++) {
                int m = warpM * 64 + mi * 16 + grp;
                af[mi][0] = ldtf(as[(m    ) * 20 + ks + qid]);
                af[mi][1] = ldtf(as[(m + 8) * 20 + ks + qid]);
                af[mi][2] = ldtf(as[(m    ) * 20 + ks + qid + 4]);
                af[mi][3] = ldtf(as[(m + 8) * 20 + ks + qid + 4]);
            }
            #pragma unroll
            for (int ni = 0; ni < 4; ni++) {
                int n = warpN * 32 + ni * 8 + grp;
                bf[ni][0] = ldtf(bs[(ks + qid    ) * 136 + n]);
                bf[ni][1] = ldtf(bs[(ks + qid + 4) * 136 + n]);
            }
            #pragma unroll
            for (int mi = 0; mi < 4; mi++)
                #pragma unroll
                for (int ni = 0; ni < 4; ni++)
                    MMA_TF32(acc[mi][ni], af[mi], bf[ni]);
        }
    };

    auto compute_t = [&](const float* __restrict__ at, const float* __restrict__ bs) {
        #pragma unroll
        for (int ks = 0; ks < 16; ks += 8) {
            uint32_t af[4][4], bf[4][2];
            #pragma unroll
            for (int mi = 0; mi < 4; mi++) {
                int m = warpM * 64 + mi * 16 + grp;
                af[mi][0] = ldtf(at[(ks + qid    ) * 136 + m]);
                af[mi][1] = ldtf(at[(ks + qid    ) * 136 + m + 8]);
                af[mi][2] = ldtf(at[(ks + qid + 4) * 136 + m]);
                af[mi][3] = ldtf(at[(ks + qid + 4) * 136 + m + 8]);
            }
            #pragma unroll
            for (int ni = 0; ni < 4; ni++) {
                int n = warpN * 32 + ni * 8 + grp;
                bf[ni][0] = ldtf(bs[(ks + qid    ) * 136 + n]);
                bf[ni][1] = ldtf(bs[(ks + qid + 4) * 136 + n]);
            }
            #pragma unroll
            for (int mi = 0; mi < 4; mi++)
                #pragma unroll
                for (int ni = 0; ni < 4; ni++)
                    MMA_TF32(acc[mi][ni], af[mi], bf[ni]);
        }
    };

    // ---- Phase A: 16 virtual tiles (xh/cw0 then tx1/cw1) ----
    zero_acc();
    issue_ab(xh, cw0, 0, 0);
    #pragma unroll 1
    for (int t = 0; t < 16; t++) {
        CP_WAIT(0);
        __syncthreads();
        int tn = t + 1;
        if (tn < 16) {
            const float* An = (tn < 8) ? xh  : tx1;
            const float* Bn = (tn < 8) ? cw0 : cw1;
            issue_ab(An, Bn, (tn & 7) << 4, tn & 1);
        }
        compute_s(AS + (t & 1) * A_TILE_F, BS + (t & 1) * B_TILE_F);
    }
    issue_ab(s, sw, 0, 0);   // pre-issue phase-B tile 0
    #pragma unroll
    for (int mi = 0; mi < 4; mi++)
        #pragma unroll
        for (int half = 0; half < 2; half++) {
            int rl = warpM * 64 + mi * 16 + grp + half * 8;
            #pragma unroll
            for (int ni = 0; ni < 4; ni++) {
                int col = warpN * 32 + ni * 8 + qid * 2;
                float vx = acc[mi][ni][half*2+0] + cb[col];
                float vy = acc[mi][ni][half*2+1] + cb[col+1];
                vx = (vx > 0.f) ? vx : 0.01f * vx;
                vy = (vy > 0.f) ? vy : 0.01f * vy;
                T[(col  ) * 136 + rl] = vx;
                T[(col+1) * 136 + rl] = vy;
            }
        }

    // ---- Phase B: 8 tiles of s@sw ----
    zero_acc();
    #pragma unroll 1
    for (int t = 0; t < 8; t++) {
        CP_WAIT(0);
        __syncthreads();
        if (t + 1 < 8) issue_ab(s, sw, (t + 1) << 4, (t + 1) & 1);
        compute_s(AS + (t & 1) * A_TILE_F, BS + (t & 1) * B_TILE_F);
    }
    issue_bc(lwp, 0, 0);     // pre-issue phase-C weight tile 0
    #pragma unroll
    for (int mi = 0; mi < 4; mi++)
        #pragma unroll
        for (int half = 0; half < 2; half++) {
            int rl = warpM * 64 + mi * 16 + grp + half * 8;
            #pragma unroll
            for (int ni = 0; ni < 4; ni++) {
                int col = warpN * 32 + ni * 8 + qid * 2;
                float vx = acc[mi][ni][half*2+0] + sb[col];
                float vy = acc[mi][ni][half*2+1] + sb[col+1];
                vx = (vx > 0.f) ? vx : 0.01f * vx;
                vy = (vy > 0.f) ? vy : 0.01f * vy;
                T[(col  ) * 136 + rl] += vx;
                T[(col+1) * 136 + rl] += vy;
            }
        }
    __syncthreads();

    // ---- Phase C: 8 tiles of T@W' ----
    zero_acc();
    #pragma unroll 1
    for (int t = 0; t < 8; t++) {
        CP_WAIT(0);
        __syncthreads();
        if (t + 1 < 8) issue_bc(lwp, (t + 1) << 4, (t + 1) & 1);
        compute_t(T + t * 16 * 136, BS + (t & 1) * B_TILE_F);
    }

    if (CLS == 0) {
        #pragma unroll
        for (int mi = 0; mi < 4; mi++)
            #pragma unroll
            for (int half = 0; half < 2; half++) {
                int row = r0 + warpM * 64 + mi * 16 + grp + half * 8;
                if (row >= Nrows) continue;
                #pragma unroll
                for (int ni = 0; ni < 4; ni++) {
                    int col = warpN * 32 + ni * 8 + qid * 2;
                    float vx = acc[mi][ni][half*2+0] + lbp[col];
                    float vy = acc[mi][ni][half*2+1] + lbp[col+1];
                    *(float2*)&out[(size_t)row * HH + col] = make_float2(vx, vy);
                }
            }
    } else {
        __syncthreads();
        float* L = sm;                // [128][44]
        #pragma unroll
        for (int mi = 0; mi < 4; mi++)
            #pragma unroll
            for (int half = 0; half < 2; half++) {
                int rl = warpM * 64 + mi * 16 + grp + half * 8;
                #pragma unroll
                for (int ni = 0; ni < 4; ni++) {
                    int col = warpN * 32 + ni * 8 + qid * 2;
                    if (col >= CO) continue;
                    L[rl * 44 + col    ] = acc[mi][ni][half*2+0] + lbp[col];
                    L[rl * 44 + col + 1] = acc[mi][ni][half*2+1] + lbp[col+1];
                }
            }
        __syncthreads();
        for (int r = 0; r < 16; r++) {
            int rl  = wid * 16 + r;
            int row = r0 + rl;
            if (row >= Nrows) break;
            float v0 = L[rl * 44 + lane];
            float v1 = (lane < CO - 32) ? L[rl * 44 + 32 + lane] : -3.4e38f;
            float m = fmaxf(v0, v1);
            #pragma unroll
            for (int o = 16; o > 0; o >>= 1) m = fmaxf(m, __shfl_xor_sync(0xffffffffu, m, o));
            float e = expf(v0 - m) + ((lane < CO - 32) ? expf(v1 - m) : 0.0f);
            #pragma unroll
            for (int o = 16; o > 0; o >>= 1) e += __shfl_xor_sync(0xffffffffu, e, o);
            float ls = m + logf(e);
            out[(size_t)row * CO + lane] = v0 - ls;
            if (lane < CO - 32) out[(size_t)row * CO + 32 + lane] = v1 - ls;
        }
    }
}

// ---------------- launch ----------------
extern "C" void kernel_launch(void* const* d_in, const int* in_sizes, int n_in,
                              void* d_out, int out_size) {
    const float* x    = (const float*)d_in[0];
    const int*   ei   = (const int*)  d_in[1];
    const float* w    = (const float*)d_in[2];
    const float* pre_w1 = (const float*)d_in[3];
    const float* pre_b1 = (const float*)d_in[4];
    const float* cw0_1  = (const float*)d_in[5];
    const float* cw1_1  = (const float*)d_in[6];
    const float* cb_1   = (const float*)d_in[7];
    const float* sw_1   = (const float*)d_in[8];
    const float* sb_1   = (const float*)d_in[9];
    const float* lw_1   = (const float*)d_in[10];
    const float* lb_1   = (const float*)d_in[11];
    const float* pre_w2 = (const float*)d_in[12];
    const float* pre_b2 = (const float*)d_in[13];
    const float* cw0_2  = (const float*)d_in[14];
    const float* cw1_2  = (const float*)d_in[15];
    const float* cb_2   = (const float*)d_in[16];
    const float* sw_2   = (const float*)d_in[17];
    const float* sb_2   = (const float*)d_in[18];
    const float* lw_2   = (const float*)d_in[19];
    const float* lb_2   = (const float*)d_in[20];
    const float* cls_w  = (const float*)d_in[21];
    const float* cls_b  = (const float*)d_in[22];
    float* out = (float*)d_out;

    void *p_xh, *p_tx1, *p_s, *p_xc, *p_w1p, *p_b1p, *p_w2p, *p_b2p;
    cudaGetSymbolAddress(&p_xh,  g_xh);
    cudaGetSymbolAddress(&p_tx1, g_tx1);
    cudaGetSymbolAddress(&p_s,   g_s);
    cudaGetSymbolAddress(&p_xc,  g_xc);
    cudaGetSymbolAddress(&p_w1p, g_w1p);
    cudaGetSymbolAddress(&p_b1p, g_b1p);
    cudaGetSymbolAddress(&p_w2p, g_w2p);
    cudaGetSymbolAddress(&p_b2p, g_b2p);
    float* xh  = (float*)p_xh;
    float* tx1 = (float*)p_tx1;
    float* s   = (float*)p_s;
    float* xc  = (float*)p_xc;
    float* w1p = (float*)p_w1p;
    float* b1p = (float*)p_b1p;
    float* w2p = (float*)p_w2p;
    float* b2p = (float*)p_b2p;

    static bool attr_done = false;
    if (!attr_done) {
        cudaFuncSetAttribute(cell_post_kernel<0>,
                             cudaFuncAttributeMaxDynamicSharedMemorySize, SMEM_MEGA);
        cudaFuncSetAttribute(cell_post_kernel<1>,
                             cudaFuncAttributeMaxDynamicSharedMemorySize, SMEM_MEGA);
        cudaFuncSetAttribute(gemm_pre_zero_kernel,
                             cudaFuncAttributeMaxDynamicSharedMemorySize, SMEM_GEMM);
        attr_done = true;
    }

    // 1: gemm + zero + fuse_w + fuse_bias (independent tails)
    gemm_pre_zero_kernel<<<GB_TOTAL, 256, SMEM_GEMM>>>(
        x, pre_w1, pre_b1, xh, NN, FIN,
        lw_1, pre_w2, lw_2, cls_w, lb_1, pre_b2, lb_2, cls_b);
    // 2: edge histogram / degree
    prep_edge_kernel<<<(NE + 255)/256, 256>>>(ei, w);
    // 3: scan block sums
    scan1_kernel<<<160, 256>>>();
    // 4: rowptr emit + node prep
    scan3m_kernel<<<160, 256>>>();
    // 5: CSR fill
    fill_kernel<<<(NE + 255)/256, 256>>>(ei, w);
    // 6: aggregate (cell 1)
    aggregate_kernel<<<(NN * 32 + 255) / 256, 256>>>((const float4*)xh, (float4*)tx1, (float4*)s);
    // 7: cell 1 post (emits cell-2's xh via W1')
    cell_post_kernel<0><<<GB_GEMM, 256, SMEM_MEGA>>>(xh, tx1, s, cw0_1, cw1_1, cb_1,
                                                     sw_1, sb_1, w1p, b1p, xc, NN);
    // 8: aggregate (cell 2)
    aggregate_kernel<<<(NN * 32 + 255) / 256, 256>>>((const float4*)xc, (float4*)tx1, (float4*)s);
    // 9: cell 2 post (emits logits + log_softmax)
    cell_post_kernel<1><<<GB_GEMM, 256, SMEM_MEGA>>>(xc, tx1, s, cw0_2, cw1_2, cb_2,
                                                     sw_2, sb_2, w2p, b2p, out, NN);
}